// round 4
// baseline (speedup 1.0000x reference)
#include <cuda_runtime.h>

#define BATCH  16384
#define TSTEPS 60
#define HDIM   50
#define BLOCK  224          // 7 warps; 200 unit threads (4 gates x 50 k)
#define ELPB   128          // elements per block
#define EPS    64           // element pairs
#define GRID   (BATCH / ELPB)

typedef unsigned long long ull;

// shared layout in ull units
#define OFF_H0  0
#define OFF_H1  (OFF_H0 + EPS * HDIM)      // 3200
#define OFF_C   (OFF_H1 + EPS * HDIM)      // 6400
#define OFF_O   (OFF_C  + EPS * HDIM)      // 9600
#define OFF_X   (OFF_O  + EPS * HDIM)      // 12800
#define OFF_WL  (OFF_X  + EPS * TSTEPS)    // 16640
#define OFF_SCR (OFF_WL + TSTEPS * HDIM)   // 19640
#define SMEM_ULL (OFF_SCR + 2)             // 19642 ull = 157,136 B

__device__ __forceinline__ float ex2f(float x) {
    float r; asm("ex2.approx.f32 %0, %1;" : "=f"(r) : "f"(x)); return r;
}
__device__ __forceinline__ float rcpf(float x) {
    float r; asm("rcp.approx.f32 %0, %1;" : "=f"(r) : "f"(x)); return r;
}
__device__ __forceinline__ void ffma2(ull& d, ull a, ull b) {
    asm("fma.rn.f32x2 %0, %1, %2, %0;" : "+l"(d) : "l"(a), "l"(b));
}
__device__ __forceinline__ ull addf2(ull a, ull b) {
    ull r; asm("add.rn.f32x2 %0, %1, %2;" : "=l"(r) : "l"(a), "l"(b)); return r;
}
__device__ __forceinline__ ull packf2(float lo, float hi) {
    ull r; asm("mov.b64 %0, {%1, %2};" : "=l"(r) : "f"(lo), "f"(hi)); return r;
}
__device__ __forceinline__ void unpackf2(ull v, float& lo, float& hi) {
    asm("mov.b64 {%0, %1}, %2;" : "=f"(lo), "=f"(hi) : "l"(v));
}

__global__ void __launch_bounds__(BLOCK, 1)
lstm_tr_kernel(const float* __restrict__ x_g,
               const float* __restrict__ wih_g,
               const float* __restrict__ whh_g,
               const float* __restrict__ bih_g,
               const float* __restrict__ bhh_g,
               const float* __restrict__ wlin_g,
               const float* __restrict__ blin_g,
               float* __restrict__ out_g)
{
    extern __shared__ ull sm[];
    const int tid = threadIdx.x;

    // ---------- staging ----------
    {
        const float* xin = x_g + (size_t)blockIdx.x * ELPB * TSTEPS;
        for (int idx = tid; idx < EPS * TSTEPS; idx += BLOCK) {
            int ep = idx / TSTEPS, t = idx % TSTEPS;
            float lo = xin[(2 * ep    ) * TSTEPS + t];
            float hi = xin[(2 * ep + 1) * TSTEPS + t];
            sm[OFF_X + ep * TSTEPS + t] = packf2(lo, hi);
        }
        for (int idx = tid; idx < TSTEPS * HDIM; idx += BLOCK) {
            float w = wlin_g[idx];
            sm[OFF_WL + idx] = packf2(w, w);
        }
        for (int idx = tid; idx < EPS * HDIM; idx += BLOCK) {
            sm[OFF_H0 + idx] = 0ull;
            sm[OFF_C  + idx] = 0ull;
            sm[OFF_O  + idx] = 0ull;
        }
        if (tid < 2) sm[OFF_SCR + tid] = 0ull;
    }

    // ---------- per-thread unit setup ----------
    const bool active = (tid < 4 * HDIM);
    const int  kk  = active ? (tid >> 2) : 0;
    const int  g   = tid & 3;                       // 0:i 1:g 2:f 3:o
    const int  row = kk + ((g == 1) ? 100 : (g == 2) ? 50 : (g == 3) ? 150 : 0);

    ull wreg[HDIM];
#pragma unroll
    for (int j = 0; j < HDIM; j++) {
        float w = active ? whh_g[row * HDIM + j] : 0.0f;
        wreg[j] = packf2(w, w);
    }
    const float wih_s = active ? wih_g[row] : 0.0f;
    const float bsum  = active ? (bih_g[row] + bhh_g[row]) : 0.0f;

    const float Lc = 1.4426950408889634f;
    const bool  isT = (g == 1);
    const float M0 = isT ? -2.0f * Lc : -Lc;
    const float S0 = isT ?  2.0f      :  1.0f;
    const float B0 = isT ? -1.0f      :  0.0f;

    __syncthreads();

    ull* const hb0 = sm + OFF_H0;
    ull* const hb1 = sm + OFF_H1;
    ull* const cb  = sm + OFF_C;
    ull* const ob  = sm + OFF_O;

    // ---------- recurrence ----------
    for (int t = 0; t < TSTEPS; t++) {
        const ull* hold = (t & 1) ? hb1 : hb0;
        ull*       hnew = (t & 1) ? hb0 : hb1;
        const ull* wl2  = sm + OFF_WL + t * HDIM;

        for (int ep = 0; ep < EPS; ep++) {
            // x projection init
            float x0, x1;
            unpackf2(sm[OFF_X + ep * TSTEPS + t], x0, x1);
            ull acc0 = packf2(fmaf(x0, wih_s, bsum), fmaf(x1, wih_s, bsum));
            ull acc1 = 0ull, acc2 = 0ull, acc3 = 0ull;

            const ulonglong2* hp = (const ulonglong2*)(hold + ep * HDIM);
#pragma unroll
            for (int jj = 0; jj < 12; jj++) {
                const ulonglong2 a = hp[2 * jj];
                const ulonglong2 b = hp[2 * jj + 1];
                ffma2(acc0, a.x, wreg[4 * jj]);
                ffma2(acc1, a.y, wreg[4 * jj + 1]);
                ffma2(acc2, b.x, wreg[4 * jj + 2]);
                ffma2(acc3, b.y, wreg[4 * jj + 3]);
            }
            {
                const ulonglong2 a = hp[24];
                ffma2(acc0, a.x, wreg[48]);
                ffma2(acc1, a.y, wreg[49]);
            }
            float s0, s1;
            unpackf2(addf2(addf2(acc0, acc1), addf2(acc2, acc3)), s0, s1);

            // own gate activation (sigmoid for i,f,o; tanh for g)
            const float act0 = fmaf(S0, rcpf(1.0f + ex2f(M0 * s0)), B0);
            const float act1 = fmaf(S0, rcpf(1.0f + ex2f(M0 * s1)), B0);

            // q = partner gate within (i,g) / (f,o)
            const float q0 = __shfl_xor_sync(0xffffffffu, act0, 1);
            const float q1 = __shfl_xor_sync(0xffffffffu, act1, 1);

            // v: p0/p1 -> i*g ; p2/p3 -> f*c
            float c0, c1;
            unpackf2(cb[ep * HDIM + kk], c0, c1);
            const float f0 = (g == 2) ? act0 : q0;   // f on p2/p3
            const float f1 = (g == 2) ? act1 : q1;
            const float v0 = (g >= 2) ? f0 * c0 : act0 * q0;
            const float v1 = (g >= 2) ? f1 * c1 : act1 * q1;

            const float w0 = __shfl_xor_sync(0xffffffffu, v0, 2);
            const float w1 = __shfl_xor_sync(0xffffffffu, v1, 2);
            const float cn0 = v0 + w0;               // ig + fc on all lanes
            const float cn1 = v1 + w1;

            // distribute o to all lanes
            const float r0  = __shfl_xor_sync(0xffffffffu, q0, 2);
            const float r1  = __shfl_xor_sync(0xffffffffu, q1, 2);
            const float rb0 = __shfl_xor_sync(0xffffffffu, r0, 1);
            const float rb1 = __shfl_xor_sync(0xffffffffu, r1, 1);
            const float o0 = (g == 0) ? r0 : (g == 1) ? rb0 : (g == 2) ? q0 : act0;
            const float o1 = (g == 0) ? r1 : (g == 1) ? rb1 : (g == 2) ? q1 : act1;

            const float th0 = fmaf(2.0f, rcpf(1.0f + ex2f(-2.0f * Lc * cn0)), -1.0f);
            const float th1 = fmaf(2.0f, rcpf(1.0f + ex2f(-2.0f * Lc * cn1)), -1.0f);
            const float hv0 = th0 * o0;
            const float hv1 = th1 * o1;

            const ull hvp = packf2(hv0, hv1);
            const ull cnp = packf2(cn0, cn1);

            // output partial (RMW; g2 lane stores it)
            ull op = ob[ep * HDIM + kk];
            ffma2(op, hvp, wl2[kk]);

            // branch-free store: g0->c, g1/g3->h_new, g2->out partial
            ull val = (g == 0) ? cnp : (g == 2) ? op : hvp;
            ull* addr = (g == 0) ? (cb + ep * HDIM + kk)
                      : (g == 2) ? (ob + ep * HDIM + kk)
                      :            (hnew + ep * HDIM + kk);
            if (!active) addr = sm + OFF_SCR;        // select, no branch body
            *addr = val;
        }
        __syncthreads();
    }

    // ---------- final reduction of output partials ----------
    for (int e = tid; e < ELPB; e += BLOCK) {
        const int ep = e >> 1, half = e & 1;
        const float* obf = (const float*)(sm + OFF_O);
        float s = 0.0f;
#pragma unroll
        for (int kx = 0; kx < HDIM; kx++)
            s += obf[(ep * HDIM + kx) * 2 + half];
        out_g[(size_t)blockIdx.x * ELPB + e] = s + blin_g[0];
    }
}

extern "C" void kernel_launch(void* const* d_in, const int* in_sizes, int n_in,
                              void* d_out, int out_size)
{
    const float* x    = (const float*)d_in[0];
    const float* wih  = (const float*)d_in[1];
    const float* whh  = (const float*)d_in[2];
    const float* bih  = (const float*)d_in[3];
    const float* bhh  = (const float*)d_in[4];
    const float* wlin = (const float*)d_in[5];
    const float* blin = (const float*)d_in[6];
    float* out = (float*)d_out;

    const size_t smem_bytes = (size_t)SMEM_ULL * sizeof(ull);
    cudaFuncSetAttribute(lstm_tr_kernel,
                         cudaFuncAttributeMaxDynamicSharedMemorySize,
                         (int)smem_bytes);
    lstm_tr_kernel<<<GRID, BLOCK, smem_bytes>>>(x, wih, whh, bih, bhh,
                                                wlin, blin, out);
}

// round 6
// speedup vs baseline: 3.6314x; 3.6314x over previous
#include <cuda_runtime.h>
#include <cuda_bf16.h>
#include <cstdint>

#define TSTEPS 60
#define HDIM   50
#define BLOCK  256
#define ELPB   128
#define GRID   128
#define NTT    26            // n-tiles of 8 cols (200 real + 8 pad)
#define DSTRIDE 212          // D row stride in floats (208 cols + pad)

// ---- smem byte layout ----
#define ABASE  0
#define ASPLIT 16384                       // per split: 8mt*4kt*32lanes*16B
#define BBASE  (2 * ASPLIT)                // 32768
#define BSPLIT (NTT * 4 * 32 * 8)          // 26624 per split
#define DBASE  (BBASE + 2 * BSPLIT)        // 86016
#define WLBASE (DBASE + ELPB * DSTRIDE * 4) // 86016 + 108544 = 194560
#define SMTOT  (WLBASE + TSTEPS * HDIM * 4) // 206560

__device__ __forceinline__ float ex2f(float x) {
    float r; asm("ex2.approx.f32 %0, %1;" : "=f"(r) : "f"(x)); return r;
}
__device__ __forceinline__ float rcpf(float x) {
    float r; asm("rcp.approx.f32 %0, %1;" : "=f"(r) : "f"(x)); return r;
}
__device__ __forceinline__ float sigf(float x) {
    return rcpf(1.0f + ex2f(-1.4426950408889634f * x));
}
__device__ __forceinline__ float tanhf_a(float x) {
    return fmaf(2.0f, rcpf(1.0f + ex2f(-2.8853900817779268f * x)), -1.0f);
}
__device__ __forceinline__ void mma16816(float* d, const uint32_t* a, const uint32_t* b) {
    asm volatile(
        "mma.sync.aligned.m16n8k16.row.col.f32.bf16.bf16.f32 "
        "{%0,%1,%2,%3}, {%4,%5,%6,%7}, {%8,%9}, {%0,%1,%2,%3};"
        : "+f"(d[0]), "+f"(d[1]), "+f"(d[2]), "+f"(d[3])
        : "r"(a[0]), "r"(a[1]), "r"(a[2]), "r"(a[3]), "r"(b[0]), "r"(b[1]));
}

// store one A column-pair (k even: cols k,k+1) for element row e, as bf16 hi+lo frags
__device__ __forceinline__ void store_apair(char* sm, int e, int k, float v0, float v1) {
    const int mt  = e >> 4;
    const int kt  = k >> 4, kin = k & 15;
    const int tig = (kin >> 1) & 3;
    const int ridx = (((e & 15) >= 8) ? 1 : 0) + ((kin >= 8) ? 2 : 0);
    const int lt  = (e & 7) * 4 + tig;
    uint32_t hreg;
    asm("cvt.rn.bf16x2.f32 %0, %1, %2;" : "=r"(hreg) : "f"(v1), "f"(v0));
    const float b0 = __uint_as_float(hreg << 16);
    const float b1 = __uint_as_float(hreg & 0xffff0000u);
    const float l0 = v0 - b0, l1 = v1 - b1;
    uint32_t lreg;
    asm("cvt.rn.bf16x2.f32 %0, %1, %2;" : "=r"(lreg) : "f"(l1), "f"(l0));
    const int base = (mt * 4 + kt) * 512 + lt * 16 + ridx * 4;
    *(uint32_t*)(sm + ABASE + base)          = hreg;
    *(uint32_t*)(sm + ABASE + ASPLIT + base) = lreg;
}

__global__ void __launch_bounds__(BLOCK, 1)
lstm_mma_kernel(const float* __restrict__ x_g,
                const float* __restrict__ wih_g,
                const float* __restrict__ whh_g,
                const float* __restrict__ bih_g,
                const float* __restrict__ bhh_g,
                const float* __restrict__ wlin_g,
                const float* __restrict__ blin_g,
                float* __restrict__ out_g)
{
    extern __shared__ char sm[];
    const int tid  = threadIdx.x;
    const int lane = tid & 31;
    const int wid  = tid >> 5;

    // ---- zero A frag buffers (both splits) ----
    for (int i = tid; i < (2 * ASPLIT) / 16; i += BLOCK)
        ((uint4*)(sm + ABASE))[i] = make_uint4(0, 0, 0, 0);

    // ---- build B fragments (once): [s][nt][kt][lane] uint2 ----
    for (int idx = tid; idx < 2 * NTT * 4 * 32; idx += BLOCK) {
        const int s  = idx / (NTT * 4 * 32);
        int r        = idx % (NTT * 4 * 32);
        const int nt = r / 128;  r %= 128;
        const int kt = r / 32;
        const int ln = r % 32;
        const int gr = ln >> 2, tig = ln & 3;
        const int n  = nt * 8 + gr;
        const int kk[4] = {kt * 16 + 2 * tig,     kt * 16 + 2 * tig + 1,
                           kt * 16 + 2 * tig + 8, kt * 16 + 2 * tig + 9};
        unsigned short v[4];
#pragma unroll
        for (int j = 0; j < 4; j++) {
            float w = 0.0f;
            if (n < 200) {
                const int g = n & 3, cell = n >> 2;
                const int row = (g == 0 ? 0 : g == 1 ? 50 : g == 2 ? 100 : 150) + cell;
                const int k = kk[j];
                if (k < HDIM)       w = whh_g[row * HDIM + k];
                else if (k == 50)   w = bih_g[row] + bhh_g[row];
                else if (k == 51)   w = wih_g[row];
            }
            const __nv_bfloat16 hi = __float2bfloat16(w);
            v[j] = (s == 0) ? __bfloat16_as_ushort(hi)
                            : __bfloat16_as_ushort(__float2bfloat16(w - __bfloat162float(hi)));
        }
        uint2 val;
        val.x = ((uint32_t)v[1] << 16) | v[0];
        val.y = ((uint32_t)v[3] << 16) | v[2];
        *(uint2*)(sm + BBASE + s * BSPLIT + (nt * 4 + kt) * 256 + ln * 8) = val;
    }

    for (int i = tid; i < TSTEPS * HDIM; i += BLOCK)
        ((float*)(sm + WLBASE))[i] = wlin_g[i];

    __syncthreads();

    // init A cols (50,51) = (1, x_0)
    if (tid < ELPB) {
        const float x0 = x_g[((size_t)blockIdx.x * ELPB + tid) * TSTEPS];
        store_apair(sm, tid, 50, 1.0f, x0);
    }
    __syncthreads();

    // ---- per-thread state ----
    const int e = tid >> 1, q = tid & 1;
    const int kbase = q ? 26 : 0;
    const size_t ge = (size_t)blockIdx.x * ELPB + e;
    float c[26];
#pragma unroll
    for (int i = 0; i < 26; i++) c[i] = 0.0f;
    float acc = 0.0f;

    for (int t = 0; t < TSTEPS; t++) {
        // ================= GEMM phase: D = A @ B (3 split products) =========
        {
            uint32_t a0[4][4], a1[4][4];
#pragma unroll
            for (int kt = 0; kt < 4; kt++) {
                *(uint4*)a0[kt] = *(const uint4*)(sm + ABASE + (wid * 4 + kt) * 512 + lane * 16);
                *(uint4*)a1[kt] = *(const uint4*)(sm + ABASE + ASPLIT + (wid * 4 + kt) * 512 + lane * 16);
            }
            const int gr = lane >> 2, tig = lane & 3;
            float* Dp = (float*)(sm + DBASE);
#pragma unroll
            for (int np = 0; np < NTT / 2; np++) {
                float d[2][3][4];
#pragma unroll
                for (int u = 0; u < 2; u++)
#pragma unroll
                    for (int ch = 0; ch < 3; ch++)
#pragma unroll
                        for (int i = 0; i < 4; i++) d[u][ch][i] = 0.0f;

                uint32_t b0[2][4][2], b1[2][4][2];
#pragma unroll
                for (int u = 0; u < 2; u++) {
                    const int nt = 2 * np + u;
#pragma unroll
                    for (int kt = 0; kt < 4; kt++) {
                        *(uint2*)b0[u][kt] = *(const uint2*)(sm + BBASE + (nt * 4 + kt) * 256 + lane * 8);
                        *(uint2*)b1[u][kt] = *(const uint2*)(sm + BBASE + BSPLIT + (nt * 4 + kt) * 256 + lane * 8);
                    }
                }
#pragma unroll
                for (int kt = 0; kt < 4; kt++)
#pragma unroll
                    for (int u = 0; u < 2; u++) {
                        mma16816(d[u][0], a0[kt], b0[u][kt]);
                        mma16816(d[u][1], a0[kt], b1[u][kt]);
                        mma16816(d[u][2], a1[kt], b0[u][kt]);
                    }
#pragma unroll
                for (int u = 0; u < 2; u++) {
                    const int nt = 2 * np + u;
                    const int r0 = wid * 16 + gr, col = nt * 8 + 2 * tig;
                    const float s0 = d[u][0][0] + d[u][1][0] + d[u][2][0];
                    const float s1 = d[u][0][1] + d[u][1][1] + d[u][2][1];
                    const float s2 = d[u][0][2] + d[u][1][2] + d[u][2][2];
                    const float s3 = d[u][0][3] + d[u][1][3] + d[u][2][3];
                    *(float2*)(Dp + (size_t)r0 * DSTRIDE + col)       = make_float2(s0, s1);
                    *(float2*)(Dp + (size_t)(r0 + 8) * DSTRIDE + col) = make_float2(s2, s3);
                }
            }
        }
        __syncthreads();

        // ================= epilogue phase ===================================
        {
            const float* Drow = (const float*)(sm + DBASE) + (size_t)e * DSTRIDE;
            const float* wl   = (const float*)(sm + WLBASE) + t * HDIM;
#pragma unroll
            for (int p = 0; p < 12; p++) {
                const int k = kbase + 2 * p;
                const float4 gA = *(const float4*)(Drow + 4 * k);
                const float4 gB = *(const float4*)(Drow + 4 * k + 4);
                const float i0 = sigf(gA.x), f0 = sigf(gA.y);
                const float t0 = tanhf_a(gA.z), o0 = sigf(gA.w);
                c[2 * p] = fmaf(f0, c[2 * p], i0 * t0);
                const float h0 = o0 * tanhf_a(c[2 * p]);
                const float i1 = sigf(gB.x), f1 = sigf(gB.y);
                const float t1 = tanhf_a(gB.z), o1 = sigf(gB.w);
                c[2 * p + 1] = fmaf(f1, c[2 * p + 1], i1 * t1);
                const float h1 = o1 * tanhf_a(c[2 * p + 1]);
                acc = fmaf(h0, wl[k], acc);
                acc = fmaf(h1, wl[k + 1], acc);
                store_apair(sm, e, k, h0, h1);
            }
            if (q == 0) {                       // tail cells 24,25
                const int k = 24;
                const float4 gA = *(const float4*)(Drow + 4 * k);
                const float4 gB = *(const float4*)(Drow + 4 * k + 4);
                const float i0 = sigf(gA.x), f0 = sigf(gA.y);
                const float t0 = tanhf_a(gA.z), o0 = sigf(gA.w);
                c[24] = fmaf(f0, c[24], i0 * t0);
                const float h0 = o0 * tanhf_a(c[24]);
                const float i1 = sigf(gB.x), f1 = sigf(gB.y);
                const float t1 = tanhf_a(gB.z), o1 = sigf(gB.w);
                c[25] = fmaf(f1, c[25], i1 * t1);
                const float h1 = o1 * tanhf_a(c[25]);
                acc = fmaf(h0, wl[k], acc);
                acc = fmaf(h1, wl[k + 1], acc);
                store_apair(sm, e, k, h0, h1);
            } else if (t + 1 < TSTEPS) {        // refresh (1, x_{t+1})
                const float xn = x_g[ge * TSTEPS + t + 1];
                store_apair(sm, e, 50, 1.0f, xn);
            }
        }
        __syncthreads();
    }

    acc += __shfl_xor_sync(0xffffffffu, acc, 1);
    if (q == 0) out_g[ge] = acc + blin_g[0];
}

extern "C" void kernel_launch(void* const* d_in, const int* in_sizes, int n_in,
                              void* d_out, int out_size)
{
    const float* x    = (const float*)d_in[0];
    const float* wih  = (const float*)d_in[1];
    const float* whh  = (const float*)d_in[2];
    const float* bih  = (const float*)d_in[3];
    const float* bhh  = (const float*)d_in[4];
    const float* wlin = (const float*)d_in[5];
    const float* blin = (const float*)d_in[6];
    float* out = (float*)d_out;

    cudaFuncSetAttribute(lstm_mma_kernel,
                         cudaFuncAttributeMaxDynamicSharedMemorySize, SMTOT);
    lstm_mma_kernel<<<GRID, BLOCK, SMTOT>>>(x, wih, whh, bih, bhh, wlin, blin, out);
}